// round 17
// baseline (speedup 1.0000x reference)
#include <cuda_runtime.h>
#include <math.h>
#include <cstdint>

// ---------------------------------------------------------------------------
// AttentionLayer: B=64, L=R=512, H=512, D=256
//   T_lt = tanh(lstm_lt @ W) * diagW ; T_rt = tanh(lstm_rt @ W)
//   S[b,l,r] = sum_d T_lt[b,l,d]*T_rt[b,r,d] ; out = softmax(S, -1)
// R17: proj_kernel = measured R13 FFMA2 version (303us). Score GEMM fused
// with softmax (64x512 tiles); thread columns interleaved at 32-float stride
// for conflict-free B-fragment LDS.128 (R16 had a 4-way bank conflict).
// tcgen05 unreachable in this toolchain (ptxas targets sm_103).
// ---------------------------------------------------------------------------

#define BDIM 64
#define LDIM 512
#define RDIM 512
#define HDIM 512
#define DDIM 256
#define MROWS 32768            // rows per projection (64*512)

typedef unsigned long long ull;

#define FMA_F32X2(d, a, b, c) \
    asm("fma.rn.f32x2 %0, %1, %2, %3;" : "=l"(d) : "l"(a), "l"(b), "l"(c))
#define PACK_DUP(out, x) \
    asm("mov.b64 %0, {%1, %1};" : "=l"(out) : "f"(x))
#define UNPACK2(lo, hi, v) \
    asm("mov.b64 {%0, %1}, %2;" : "=f"(lo), "=f"(hi) : "l"(v))
#define MICRO_ROW(acci, a_scalar) do {                     \
    ull _a2; PACK_DUP(_a2, a_scalar);                      \
    FMA_F32X2((acci)[0], _a2, bv0, (acci)[0]);             \
    FMA_F32X2((acci)[1], _a2, bv1, (acci)[1]);             \
    FMA_F32X2((acci)[2], _a2, bv2, (acci)[2]);             \
    FMA_F32X2((acci)[3], _a2, bv3, (acci)[3]);             \
} while (0)
// 8-pair variant (16 cols per thread-row) for the fused score kernel.
#define MICRO_ROW8(acci, a_scalar) do {                    \
    ull _a2; PACK_DUP(_a2, a_scalar);                      \
    FMA_F32X2((acci)[0], _a2, bv0, (acci)[0]);             \
    FMA_F32X2((acci)[1], _a2, bv1, (acci)[1]);             \
    FMA_F32X2((acci)[2], _a2, bv2, (acci)[2]);             \
    FMA_F32X2((acci)[3], _a2, bv3, (acci)[3]);             \
    FMA_F32X2((acci)[4], _a2, bv4, (acci)[4]);             \
    FMA_F32X2((acci)[5], _a2, bv5, (acci)[5]);             \
    FMA_F32X2((acci)[6], _a2, bv6, (acci)[6]);             \
    FMA_F32X2((acci)[7], _a2, bv7, (acci)[7]);             \
} while (0)

__device__ __forceinline__ float fast_tanh(float x)
{ float y; asm("tanh.approx.f32 %0, %1;" : "=f"(y) : "f"(x)); return y; }
__device__ __forceinline__ float fast_rcp(float x)
{ float y; asm("rcp.approx.f32 %0, %1;" : "=f"(y) : "f"(x)); return y; }

// Scratch: both projection outputs (lt rows [0,32768), rt rows [32768,65536)).
__device__ float g_T[(size_t)2 * MROWS * DDIM];

// ---------------------------------------------------------------------------
// Fused projection GEMM (NN), R13 measured version: combined M = 65536.
// ---------------------------------------------------------------------------
#define TB 256
#define BM 128
#define BN 128
#define BK 16
#define TM 8

__global__ __launch_bounds__(TB, 2)
void proj_kernel(const float* __restrict__ Alt, const float* __restrict__ Art,
                 const float* __restrict__ W, const float* __restrict__ dW,
                 float* __restrict__ C)
{
    const int K = HDIM, N = DDIM;
    __shared__ __align__(16) float As[2][BK][BM + 4];
    __shared__ __align__(16) float Bs[2][BK][BN];

    const int bm = blockIdx.y * BM;
    const bool isLt = (bm < MROWS);
    const float* __restrict__ A = isLt ? Alt : Art;
    const int bmLocal = isLt ? bm : (bm - MROWS);

    const int bn = blockIdx.x * BN;
    const int tid = threadIdx.x;
    const int tx = tid % 16;
    const int ty = tid / 16;

    const int a_row0 = (tid + 0 * TB) >> 2;
    const int a_kq0  = ((tid + 0 * TB) & 3) * 4;
    const int a_row1 = (tid + 1 * TB) >> 2;
    const int a_kq1  = ((tid + 1 * TB) & 3) * 4;
    const int b_row0 = (tid + 0 * TB) >> 5;
    const int b_c40  = ((tid + 0 * TB) & 31) * 4;
    const int b_row1 = (tid + 1 * TB) >> 5;
    const int b_c41  = ((tid + 1 * TB) & 31) * 4;

    const float* __restrict__ pA0 = &A[(size_t)(bmLocal + a_row0) * K];
    const float* __restrict__ pA1 = &A[(size_t)(bmLocal + a_row1) * K];

    ull acc2[TM][4];
    #pragma unroll
    for (int i = 0; i < TM; i++)
        #pragma unroll
        for (int j = 0; j < 4; j++) acc2[i][j] = 0ull;

    {
        float4 va0 = *reinterpret_cast<const float4*>(&pA0[a_kq0]);
        float4 va1 = *reinterpret_cast<const float4*>(&pA1[a_kq1]);
        float4 vb0 = *reinterpret_cast<const float4*>(&W[(size_t)(b_row0) * N + bn + b_c40]);
        float4 vb1 = *reinterpret_cast<const float4*>(&W[(size_t)(b_row1) * N + bn + b_c41]);
        As[0][a_kq0 + 0][a_row0] = va0.x; As[0][a_kq0 + 1][a_row0] = va0.y;
        As[0][a_kq0 + 2][a_row0] = va0.z; As[0][a_kq0 + 3][a_row0] = va0.w;
        As[0][a_kq1 + 0][a_row1] = va1.x; As[0][a_kq1 + 1][a_row1] = va1.y;
        As[0][a_kq1 + 2][a_row1] = va1.z; As[0][a_kq1 + 3][a_row1] = va1.w;
        *reinterpret_cast<float4*>(&Bs[0][b_row0][b_c40]) = vb0;
        *reinterpret_cast<float4*>(&Bs[0][b_row1][b_c41]) = vb1;
    }
    __syncthreads();

    const int NT = K / BK;   // 32
    #pragma unroll 2
    for (int kt = 0; kt < NT; kt++) {
        const int cur = kt & 1;
        const int nxt = cur ^ 1;

        float4 va0, va1, vb0, vb1;
        if (kt + 1 < NT) {
            const int k0 = (kt + 1) * BK;
            va0 = *reinterpret_cast<const float4*>(&pA0[k0 + a_kq0]);
            va1 = *reinterpret_cast<const float4*>(&pA1[k0 + a_kq1]);
            vb0 = *reinterpret_cast<const float4*>(&W[(size_t)(k0 + b_row0) * N + bn + b_c40]);
            vb1 = *reinterpret_cast<const float4*>(&W[(size_t)(k0 + b_row1) * N + bn + b_c41]);
        }

        #pragma unroll
        for (int k = 0; k < BK; k++) {
            float4 a0 = *reinterpret_cast<const float4*>(&As[cur][k][ty * TM]);
            float4 a1 = *reinterpret_cast<const float4*>(&As[cur][k][ty * TM + 4]);
            ulonglong2 bp0 = *reinterpret_cast<const ulonglong2*>(&Bs[cur][k][tx * 4]);
            ulonglong2 bp1 = *reinterpret_cast<const ulonglong2*>(&Bs[cur][k][64 + tx * 4]);
            const ull bv0 = bp0.x, bv1 = bp0.y, bv2 = bp1.x, bv3 = bp1.y;
            MICRO_ROW(acc2[0], a0.x);
            MICRO_ROW(acc2[1], a0.y);
            MICRO_ROW(acc2[2], a0.z);
            MICRO_ROW(acc2[3], a0.w);
            MICRO_ROW(acc2[4], a1.x);
            MICRO_ROW(acc2[5], a1.y);
            MICRO_ROW(acc2[6], a1.z);
            MICRO_ROW(acc2[7], a1.w);
        }

        if (kt + 1 < NT) {
            As[nxt][a_kq0 + 0][a_row0] = va0.x; As[nxt][a_kq0 + 1][a_row0] = va0.y;
            As[nxt][a_kq0 + 2][a_row0] = va0.z; As[nxt][a_kq0 + 3][a_row0] = va0.w;
            As[nxt][a_kq1 + 0][a_row1] = va1.x; As[nxt][a_kq1 + 1][a_row1] = va1.y;
            As[nxt][a_kq1 + 2][a_row1] = va1.z; As[nxt][a_kq1 + 3][a_row1] = va1.w;
            *reinterpret_cast<float4*>(&Bs[nxt][b_row0][b_c40]) = vb0;
            *reinterpret_cast<float4*>(&Bs[nxt][b_row1][b_c41]) = vb1;
        }
        __syncthreads();
    }

    const int c0 = bn + tx * 4;
    const int c1 = bn + 64 + tx * 4;
    float d0x=1.f, d0y=1.f, d0z=1.f, d0w=1.f, d1x=1.f, d1y=1.f, d1z=1.f, d1w=1.f;
    if (isLt) {
        float4 dv0 = *reinterpret_cast<const float4*>(&dW[c0]);
        float4 dv1 = *reinterpret_cast<const float4*>(&dW[c1]);
        d0x=dv0.x; d0y=dv0.y; d0z=dv0.z; d0w=dv0.w;
        d1x=dv1.x; d1y=dv1.y; d1z=dv1.z; d1w=dv1.w;
    }
    #pragma unroll
    for (int i = 0; i < TM; i++) {
        const int m = bm + ty * TM + i;
        float s0, s1, s2, s3, s4, s5, s6, s7;
        UNPACK2(s0, s1, acc2[i][0]);
        UNPACK2(s2, s3, acc2[i][1]);
        UNPACK2(s4, s5, acc2[i][2]);
        UNPACK2(s6, s7, acc2[i][3]);
        float4 o0, o1;
        o0.x = fast_tanh(s0) * d0x;
        o0.y = fast_tanh(s1) * d0y;
        o0.z = fast_tanh(s2) * d0z;
        o0.w = fast_tanh(s3) * d0w;
        o1.x = fast_tanh(s4) * d1x;
        o1.y = fast_tanh(s5) * d1y;
        o1.z = fast_tanh(s6) * d1z;
        o1.w = fast_tanh(s7) * d1w;
        *reinterpret_cast<float4*>(&C[(size_t)m * N + c0]) = o0;
        *reinterpret_cast<float4*>(&C[(size_t)m * N + c1]) = o1;
    }
}

// ---------------------------------------------------------------------------
// Fused score+softmax: per block, S-tile [64 rows x 512 cols] for one batch,
// K = 256; softmax over the full row in-kernel; single write of the output.
// Block = 512 threads; warp grid 4x4 (warp: 16 rows x 128 cols).
// Thread: 4 rows x 16 cols; cols = wc*128 + g*32 + c*4, g=0..3
// (32-float stride between groups -> conflict-free LDS.128: lanes c=0..7
//  cover banks c*4..c*4+3, all 32 banks per phase).
// ---------------------------------------------------------------------------
#define SBK 16
// dynamic smem layout (floats)
#define FS_AS    0                               // As[2][16][68]
#define FS_BS    (2 * 16 * 68)                   // Bs[2][16][516]
#define FS_RMAX  (FS_BS + 2 * 16 * 516)          // red_max[64][4]
#define FS_RSUM  (FS_RMAX + 64 * 4)              // red_sum[64][4]
#define FS_TOTAL ((FS_RSUM + 64 * 4) * 4)        // bytes

__global__ __launch_bounds__(512, 1)
void score_softmax_kernel(float* __restrict__ out)
{
    extern __shared__ __align__(16) float fsm[];
    float (*As)[SBK][68]  = reinterpret_cast<float (*)[SBK][68]>(fsm + FS_AS);
    float (*Bs)[SBK][516] = reinterpret_cast<float (*)[SBK][516]>(fsm + FS_BS);
    float (*red_max)[4]   = reinterpret_cast<float (*)[4]>(fsm + FS_RMAX);
    float (*red_sum)[4]   = reinterpret_cast<float (*)[4]>(fsm + FS_RSUM);

    const int K = DDIM;                       // 256
    const int batch = blockIdx.y;
    const int bm = blockIdx.x * 64;           // row block within batch
    const float* __restrict__ Ab = g_T + ((size_t)batch * LDIM + bm) * DDIM;
    const float* __restrict__ Bb = g_T + ((size_t)MROWS + (size_t)batch * RDIM) * DDIM;

    const int tid  = threadIdx.x;
    const int wid  = tid >> 5;
    const int lane = tid & 31;
    const int wr   = wid >> 2;                // 0..3 (row quarter)
    const int wc   = wid & 3;                 // 0..3 (col quarter)
    const int r    = lane >> 3;               // 0..3
    const int c    = lane & 7;                // 0..7
    const int row0 = wr * 16 + r * 4;         // local row base (4 rows)
    const int cbase = wc * 128 + c * 4;       // col group base (groups at +32)

    // staging coords: A tile 64x16 -> 256 float4; B tile 512x16 -> 2048 float4.
    const int a_row = tid >> 2;               // valid when tid < 256
    const int a_kq  = (tid & 3) * 4;
    const float* __restrict__ pA = &Ab[(size_t)a_row * K];

    ull acc2[4][8];                           // [row][2*g + pair]
    #pragma unroll
    for (int i = 0; i < 4; i++)
        #pragma unroll
        for (int j = 0; j < 8; j++) acc2[i][j] = 0ull;

    // ---- prologue: K-chunk 0 into buffer 0 ----
    if (tid < 256) {
        float4 v = *reinterpret_cast<const float4*>(&pA[a_kq]);
        As[0][a_kq + 0][a_row] = v.x; As[0][a_kq + 1][a_row] = v.y;
        As[0][a_kq + 2][a_row] = v.z; As[0][a_kq + 3][a_row] = v.w;
    }
    #pragma unroll
    for (int i = 0; i < 4; i++) {
        int idx = tid + i * 512;
        int row = idx >> 2;
        int kq  = (idx & 3) * 4;
        float4 v = *reinterpret_cast<const float4*>(&Bb[(size_t)row * K + kq]);
        Bs[0][kq + 0][row] = v.x; Bs[0][kq + 1][row] = v.y;
        Bs[0][kq + 2][row] = v.z; Bs[0][kq + 3][row] = v.w;
    }
    __syncthreads();

    const int NT = K / SBK;  // 16
    #pragma unroll 2
    for (int kt = 0; kt < NT; kt++) {
        const int cur = kt & 1;
        const int nxt = cur ^ 1;

        float4 va, vb[4];
        if (kt + 1 < NT) {
            const int k0 = (kt + 1) * SBK;
            if (tid < 256)
                va = *reinterpret_cast<const float4*>(&pA[k0 + a_kq]);
            #pragma unroll
            for (int i = 0; i < 4; i++) {
                int idx = tid + i * 512;
                int row = idx >> 2;
                int kq  = (idx & 3) * 4;
                vb[i] = *reinterpret_cast<const float4*>(&Bb[(size_t)row * K + k0 + kq]);
            }
        }

        #pragma unroll
        for (int k = 0; k < SBK; k++) {
            float4 a4 = *reinterpret_cast<const float4*>(&As[cur][k][row0]);
            // 4 column groups at 32-float stride: conflict-free phases.
            ulonglong2 p0 = *reinterpret_cast<const ulonglong2*>(&Bs[cur][k][cbase + 0 * 32]);
            ulonglong2 p1 = *reinterpret_cast<const ulonglong2*>(&Bs[cur][k][cbase + 1 * 32]);
            ulonglong2 p2 = *reinterpret_cast<const ulonglong2*>(&Bs[cur][k][cbase + 2 * 32]);
            ulonglong2 p3 = *reinterpret_cast<const ulonglong2*>(&Bs[cur][k][cbase + 3 * 32]);
            const ull bv0 = p0.x, bv1 = p0.y, bv2 = p1.x, bv3 = p1.y;
            const ull bv4 = p2.x, bv5 = p2.y, bv6 = p3.x, bv7 = p3.y;
            MICRO_ROW8(acc2[0], a4.x);
            MICRO_ROW8(acc2[1], a4.y);
            MICRO_ROW8(acc2[2], a4.z);
            MICRO_ROW8(acc2[3], a4.w);
        }

        if (kt + 1 < NT) {
            if (tid < 256) {
                As[nxt][a_kq + 0][a_row] = va.x; As[nxt][a_kq + 1][a_row] = va.y;
                As[nxt][a_kq + 2][a_row] = va.z; As[nxt][a_kq + 3][a_row] = va.w;
            }
            #pragma unroll
            for (int i = 0; i < 4; i++) {
                int idx = tid + i * 512;
                int row = idx >> 2;
                int kq  = (idx & 3) * 4;
                Bs[nxt][kq + 0][row] = vb[i].x; Bs[nxt][kq + 1][row] = vb[i].y;
                Bs[nxt][kq + 2][row] = vb[i].z; Bs[nxt][kq + 3][row] = vb[i].w;
            }
        }
        __syncthreads();
    }

    // ---- softmax over rows; s[i][4g+p] = col cbase + g*32 + p ----
    float s[4][16];
    #pragma unroll
    for (int i = 0; i < 4; i++)
        #pragma unroll
        for (int j = 0; j < 8; j++)
            UNPACK2(s[i][2 * j], s[i][2 * j + 1], acc2[i][j]);

    // local row max -> c-lane reduce (offsets < 8 keep r-group)
    float mx[4];
    #pragma unroll
    for (int i = 0; i < 4; i++) {
        float m = s[i][0];
        #pragma unroll
        for (int j = 1; j < 16; j++) m = fmaxf(m, s[i][j]);
        #pragma unroll
        for (int o = 1; o < 8; o <<= 1)
            m = fmaxf(m, __shfl_xor_sync(0xffffffffu, m, o));
        mx[i] = m;
    }
    if (c == 0) {
        #pragma unroll
        for (int i = 0; i < 4; i++) red_max[row0 + i][wc] = mx[i];
    }
    __syncthreads();
    #pragma unroll
    for (int i = 0; i < 4; i++) {
        mx[i] = fmaxf(fmaxf(red_max[row0 + i][0], red_max[row0 + i][1]),
                      fmaxf(red_max[row0 + i][2], red_max[row0 + i][3]));
    }

    // exp + row sum
    float sm[4];
    #pragma unroll
    for (int i = 0; i < 4; i++) {
        float acc = 0.f;
        #pragma unroll
        for (int j = 0; j < 16; j++) {
            s[i][j] = __expf(s[i][j] - mx[i]);
            acc += s[i][j];
        }
        #pragma unroll
        for (int o = 1; o < 8; o <<= 1)
            acc += __shfl_xor_sync(0xffffffffu, acc, o);
        sm[i] = acc;
    }
    if (c == 0) {
        #pragma unroll
        for (int i = 0; i < 4; i++) red_sum[row0 + i][wc] = sm[i];
    }
    __syncthreads();

    // scale + store (float4 per column group)
    float* __restrict__ Ob = out + ((size_t)batch * LDIM + bm) * RDIM;
    #pragma unroll
    for (int i = 0; i < 4; i++) {
        const float inv = fast_rcp(red_sum[row0 + i][0] + red_sum[row0 + i][1] +
                                   red_sum[row0 + i][2] + red_sum[row0 + i][3]);
        float* rowp = &Ob[(size_t)(row0 + i) * RDIM];
        #pragma unroll
        for (int g = 0; g < 4; g++) {
            float4 o;
            o.x = s[i][g * 4 + 0] * inv;
            o.y = s[i][g * 4 + 1] * inv;
            o.z = s[i][g * 4 + 2] * inv;
            o.w = s[i][g * 4 + 3] * inv;
            *reinterpret_cast<float4*>(&rowp[cbase + g * 32]) = o;
        }
    }
}

// ---------------------------------------------------------------------------
extern "C" void kernel_launch(void* const* d_in, const int* in_sizes, int n_in,
                              void* d_out, int out_size)
{
    const float* lstm_lt = (const float*)d_in[0];   // (64, 512, 512)
    const float* lstm_rt = (const float*)d_in[1];   // (64, 512, 512)
    const float* atten_W = (const float*)d_in[2];   // (512, 256)
    const float* diag_W  = (const float*)d_in[3];   // (1, 1, 256)
    float* out = (float*)d_out;                     // (64, 512, 512)

    void* pT = nullptr;
    cudaGetSymbolAddress(&pT, g_T);

    // Fused projections: combined M = 65536 rows, N = 256, K = 512.
    {
        dim3 grid(DDIM / BN, (2 * MROWS) / BM);     // (2, 512)
        proj_kernel<<<grid, TB>>>(lstm_lt, lstm_rt, atten_W, diag_W, (float*)pT);
    }

    // Fused score + softmax: per block 64x512 tile; grid (8, 64).
    {
        cudaFuncSetAttribute(score_softmax_kernel,
                             cudaFuncAttributeMaxDynamicSharedMemorySize, FS_TOTAL);
        dim3 grid(LDIM / 64, BDIM);
        score_softmax_kernel<<<grid, 512, FS_TOTAL>>>(out);
    }
}